// round 5
// baseline (speedup 1.0000x reference)
#include <cuda_runtime.h>
#include <cuda_fp16.h>
#include <math.h>

#define BATCH 8
#define H 1024
#define W 1024
#define NWIN 5
#define NIMG (NWIN * BATCH)   // 40

__device__ __constant__ int c_radii[NWIN] = {3, 7, 15, 31, 63};

// Scratch: horizontal window sums (sum x, sum x^2) packed as half2.
// Layout: [win][b][y][x]  -> 40 * 1024 * 1024 * 4B = 160 MiB.
__device__ __half2 g_hsums[(size_t)NIMG * H * W];

__device__ __forceinline__ float2 h2f(unsigned int u) {
    __half2 h = *reinterpret_cast<__half2*>(&u);
    return __half22float2(h);
}

// ---------------------------------------------------------------------------
// Pass A: per-row inclusive prefix of (x, x^2) via warp shuffles + one block
// combine, then emit the 5 horizontal clipped-window sums as half2.
// One block per (row, batch). 1024 threads.
// ---------------------------------------------------------------------------
__global__ __launch_bounds__(1024) void hpass_kernel(const float* __restrict__ x,
                                                     __half2* __restrict__ hsums) {
    const int y = blockIdx.x;
    const int b = blockIdx.y;
    const int t = threadIdx.x;
    const int lane = t & 31;
    const int wid = t >> 5;

    __shared__ float2 s_warp[32];
    __shared__ float2 s_pref[W];

    const float v = x[((size_t)b * H + y) * W + t];
    float sx = v, sy = v * v;

#pragma unroll
    for (int off = 1; off < 32; off <<= 1) {
        float ax = __shfl_up_sync(0xffffffffu, sx, off);
        float ay = __shfl_up_sync(0xffffffffu, sy, off);
        if (lane >= off) { sx += ax; sy += ay; }
    }
    if (lane == 31) s_warp[wid] = make_float2(sx, sy);
    __syncthreads();
    if (wid == 0) {
        float2 w2 = s_warp[lane];
        float wx = w2.x, wy = w2.y;
#pragma unroll
        for (int off = 1; off < 32; off <<= 1) {
            float ax = __shfl_up_sync(0xffffffffu, wx, off);
            float ay = __shfl_up_sync(0xffffffffu, wy, off);
            if (lane >= off) { wx += ax; wy += ay; }
        }
        s_warp[lane] = make_float2(wx, wy);
    }
    __syncthreads();
    if (wid > 0) {
        float2 base = s_warp[wid - 1];
        sx += base.x; sy += base.y;
    }
    s_pref[t] = make_float2(sx, sy);
    __syncthreads();

#pragma unroll
    for (int w = 0; w < NWIN; w++) {
        const int r = c_radii[w];
        const int lo = max(t - r, 0);
        const int hi = min(t + r, W - 1);
        float2 s = s_pref[hi];
        if (lo > 0) {
            float2 p = s_pref[lo - 1];
            s.x -= p.x; s.y -= p.y;
        }
        hsums[((size_t)(w * BATCH + b) * H + y) * W + t] =
            __floats2half2_rn(s.x, s.y);
    }
}

// ---------------------------------------------------------------------------
// Pass B: full-height vertical sweep. One column per thread; the last 128
// rows of the column's hsum stream live in a thread-private smem ring
// (subtract via LDS -> scratch is read from DRAM exactly once, no priming
// re-reads, no L2-lag sensitivity). 16-deep register prefetch pipeline for
// MLP; zero branches in the steady-state loop.
// grid = (W/TPB, BATCH, NWIN), block = TPB.
// ---------------------------------------------------------------------------
#define TPB 64
#define XB (W / TPB)      // 16
#define PFD 16            // prefetch depth (H % PFD == 0)
#define RING 128          // ring rows (power of two, > 2*r_max)

__global__ __launch_bounds__(TPB) void vpass_kernel(const __half2* __restrict__ hsums,
                                                    const float* __restrict__ kk,
                                                    const float* __restrict__ RR,
                                                    float* __restrict__ out) {
    __shared__ unsigned int ring[RING * TPB];   // 32 KB static

    const int w = blockIdx.z;
    const int b = blockIdx.y;
    const int t = threadIdx.x;
    const int x = blockIdx.x * TPB + t;

    const int r = c_radii[w];
    const float kw = kk[w];
    const float invR = __frcp_rn(RR[w]);

    const unsigned int* col = reinterpret_cast<const unsigned int*>(
        hsums + ((size_t)(w * BATCH + b) * H) * W) + x;
    float* o = out + (((size_t)b * NWIN + w) * H) * W + x;

    const float cnth = (float)(min(x + r, W - 1) - max(x - r, 0) + 1);

    // Zero own ring column (thread-private: no syncs needed anywhere).
#pragma unroll
    for (int i = 0; i < RING; i++) ring[i * TPB + t] = 0u;

    // Prologue: accumulate rows [0, r) so entering y the window is [y-r, y+r-1].
    float sx = 0.f, sy = 0.f;
    for (int yy = 0; yy < r; yy++) {
        unsigned int u = col[(size_t)yy * W];
        float2 f = h2f(u);
        sx += f.x; sy += f.y;
        ring[(yy & (RING - 1)) * TPB + t] = u;
    }

    // Prime the prefetch pipeline with rows [r, r+PFD).
    unsigned int pre[PFD];
#pragma unroll
    for (int i = 0; i < PFD; i++) pre[i] = col[(size_t)(r + i) * W];

    for (int y0 = 0; y0 < H; y0 += PFD) {
#pragma unroll
        for (int j = 0; j < PFD; j++) {
            const int y = y0 + j;

            // add row y+r (prefetched PFD iterations ago; 0 past bottom edge)
            unsigned int u = pre[j];
            float2 fa = h2f(u);
            sx += fa.x; sy += fa.y;
            ring[((y + r) & (RING - 1)) * TPB + t] = u;

            const float cntv = (float)(min(y + r, H - 1) - max(y - r, 0) + 1);
            const float inv = __frcp_rn(cnth * cntv);
            const float mean = sx * inv;
            const float dev = sqrtf(fmaxf(fmaf(-mean, mean, sy * inv), 1e-6f));
            o[(size_t)y * W] = mean * fmaf(kw, fmaf(dev, invR, -1.0f), 1.0f);

            // subtract row y-r from the ring (zero for y < r by construction)
            unsigned int us = ring[((y - r) & (RING - 1)) * TPB + t];
            float2 fs = h2f(us);
            sx -= fs.x; sy -= fs.y;

            // prefetch row y+r+PFD (predicated zero past the bottom edge)
            const int nrow = y + r + PFD;
            pre[j] = (nrow < H) ? col[(size_t)nrow * W] : 0u;
        }
    }
}

extern "C" void kernel_launch(void* const* d_in, const int* in_sizes, int n_in,
                              void* d_out, int out_size) {
    const float* x = (const float*)d_in[0];
    const float* k = (const float*)d_in[1];
    const float* R = (const float*)d_in[2];
    float* out = (float*)d_out;

    __half2* hsums;
    cudaGetSymbolAddress((void**)&hsums, g_hsums);

    dim3 gridA(H, BATCH);
    hpass_kernel<<<gridA, 1024>>>(x, hsums);

    dim3 gridB(XB, BATCH, NWIN);
    vpass_kernel<<<gridB, TPB>>>(hsums, k, R, out);
}